// round 15
// baseline (speedup 1.0000x reference)
#include <cuda_runtime.h>

// Geometry fixed by the reference: (2,1,192,192,192) fp32 x3 -> scalar
constexpr int BATCH = 2, D = 192, H = 192, W = 192;
constexpr int DS = H * W;
constexpr int XV = 4;                  // x-values per lane (one float4)
constexpr int YV = 2;                  // output rows per lane
constexpr int ZC = 24;                 // z planes per lane
constexpr int GX = W / XV;             // 48
constexpr int GY = H / YV;             // 96
constexpr int NZ = D / ZC;             // 8
constexpr int THREADS = 64;            // small CTAs -> wave-tail smoothing
constexpr long long NVOX = (long long)BATCH * D * H * W;
constexpr int NBLOCKS = GX * GY * NZ * BATCH * 2 / THREADS;   // 2304

__device__ double   g_accum = 0.0;
__device__ unsigned g_done  = 0;

__device__ __forceinline__ float fsqrt_a(float x) {
    float y; asm("sqrt.approx.f32 %0, %1;" : "=f"(y) : "f"(x)); return y;
}
__device__ __forceinline__ float htanh(float x) {
    float y; asm("tanh.approx.f32 %0, %1;" : "=f"(y) : "f"(x)); return y;
}

// Streaming z-partials for one output row of one image (24 regs):
//   Am/Ac = A[c-1], A[c];  Ux/Cx = Bx[c-1]+2Bx[c], Bx[c];  Uy/Cy likewise.
struct State { float Am[XV], Ac[XV], Ux[XV], Cx[XV], Uy[XV], Cy[XV]; };

// x-pass for one row: s = [1,2,1]*x, d = x[+1]-x[-1], zero-padded OOB.
// Halos are independent scalar LDGs (uncoupled issue -> full MLP).
__device__ __forceinline__ void row_sd(const float* __restrict__ p, bool ok, bool xl, bool xr,
                                       float s[XV], float d[XV]) {
    float v0 = 0.f, v1 = 0.f, v2 = 0.f, v3 = 0.f, vm = 0.f, vp = 0.f;
    if (ok) {
        float4 c = __ldg(reinterpret_cast<const float4*>(p));
        v0 = c.x; v1 = c.y; v2 = c.z; v3 = c.w;
        if (xl) vm = __ldg(p - 1);
        if (xr) vp = __ldg(p + XV);
    }
    s[0] = fmaf(2.f, v0, vm + v1);
    s[1] = fmaf(2.f, v1, v0 + v2);
    s[2] = fmaf(2.f, v2, v1 + v3);
    s[3] = fmaf(2.f, v3, v2 + vp);
    d[0] = v1 - vm;
    d[1] = v2 - v0;
    d[2] = v3 - v1;
    d[3] = vp - v2;
}

// Load + x-pass the 4 input rows (gy0-1 .. gy0+2) of one plane.
__device__ __forceinline__ void xpass4(const float* __restrict__ pc, bool zok,
                                       bool r0ok, bool r3ok, bool xl, bool xr,
                                       float s[4][XV], float d[4][XV]) {
    row_sd(pc - W,     zok && r0ok, xl, xr, s[0], d[0]);
    row_sd(pc,         zok,         xl, xr, s[1], d[1]);
    row_sd(pc + W,     zok,         xl, xr, s[2], d[2]);
    row_sd(pc + 2 * W, zok && r3ok, xl, xr, s[3], d[3]);
}

// y-fold for output row r (uses s/d rows r, r+1, r+2).
__device__ __forceinline__ void fold(const float s[4][XV], const float d[4][XV], int r,
                                     float A[XV], float Bx[XV], float By[XV]) {
#pragma unroll
    for (int j = 0; j < XV; j++) {
        A[j]  = fmaf(2.f, s[r + 1][j], s[r][j] + s[r + 2][j]);
        By[j] = s[r][j] - s[r + 2][j];
        Bx[j] = fmaf(2.f, d[r + 1][j], d[r][j] + d[r + 2][j]);
    }
}

__device__ __forceinline__ void state_init(State& st, const float A1[XV], const float Bx1[XV],
                                           const float By1[XV], const float A0[XV],
                                           const float Bx0[XV], const float By0[XV]) {
#pragma unroll
    for (int j = 0; j < XV; j++) {
        st.Am[j] = A1[j];  st.Ac[j] = A0[j];
        st.Ux[j] = fmaf(2.f, Bx0[j], Bx1[j]);  st.Cx[j] = Bx0[j];
        st.Uy[j] = fmaf(2.f, By0[j], By1[j]);  st.Cy[j] = By0[j];
    }
}

// z-combine at plane c given fresh plane c+1; advances streaming state.
__device__ __forceinline__ void step_row(State& st, const float A[XV], const float Bx[XV],
                                         const float By[XV], float msq[XV]) {
#pragma unroll
    for (int j = 0; j < XV; j++) {
        float gx = st.Ux[j] + Bx[j];
        float gy = st.Uy[j] + By[j];
        float gz = st.Am[j] - A[j];
        msq[j] = fmaf(gx, gx, fmaf(gy, gy, fmaf(gz, gz, 1e-10f)));
        st.Ux[j] = fmaf(2.f, Bx[j], st.Cx[j]);  st.Cx[j] = Bx[j];
        st.Uy[j] = fmaf(2.f, By[j], st.Cy[j]);  st.Cy[j] = By[j];
        st.Am[j] = st.Ac[j];                    st.Ac[j] = A[j];
    }
}

__global__ void __launch_bounds__(THREADS, 9)
k_loss(const float* __restrict__ pred,
       const float* __restrict__ gt,
       const float* __restrict__ mask,
       float* __restrict__ out) {
    const int gtid = blockIdx.x * THREADS + threadIdx.x;
    const int im = gtid & 1;          // 0: lane owns pred, 1: lane owns gt
    const int pr = gtid >> 1;         // pair index
    int xg  = pr % GX;
    int tq  = pr / GX;
    int yg  = tq % GY;  tq /= GY;
    int zc  = tq % NZ;
    int b   = tq / NZ;
    const int x0 = xg * XV, gy0 = yg * YV, z0 = zc * ZC;

    const bool r0ok = (gy0 > 0), r3ok = (gy0 + YV < H);
    const bool xl = (x0 > 0), xr = (x0 + XV < W);

    const float* ownBase = im ? gt : pred;
    const float* othBase = im ? pred : gt;
    const size_t cell = (size_t)b * D * DS + (size_t)gy0 * W + x0;

    const float* pI = ownBase + cell + (long long)(z0 - 1) * DS;  // own stencil walker
    const float* pO = othBase + cell + (long long)z0 * DS;        // other-image centers
    const float* pM = mask    + cell + (long long)z0 * DS;        // mask centers

    State st[YV];

    // Prologue: own image, planes z0-1 and z0
    {
        float s[4][XV], d[4][XV];
        float A1[XV], Bx1[XV], By1[XV], A0[XV], Bx0[XV], By0[XV];
        xpass4(pI, z0 > 0, r0ok, r3ok, xl, xr, s, d);
        pI += DS;
        float s2[4][XV], d2[4][XV];
        xpass4(pI, true, r0ok, r3ok, xl, xr, s2, d2);
#pragma unroll
        for (int r = 0; r < YV; r++) {
            fold(s, d, r, A1, Bx1, By1);
            fold(s2, d2, r, A0, Bx0, By0);
            state_init(st[r], A1, Bx1, By1, A0, Bx0, By0);
        }
    }

    float acc = 0.f;
#pragma unroll 2
    for (int c = z0; c < z0 + ZC; c++) {
        pI += DS;                                  // own image, plane c+1
        // plane-c centers: own (cv, L1 hit: loaded last iter by this thread),
        // other image (ov), mask (mv) -- all independent, issued early
        float4 cv[YV], ov[YV], mv[YV];
        cv[0] = __ldg(reinterpret_cast<const float4*>(pI - DS));
        cv[1] = __ldg(reinterpret_cast<const float4*>(pI - DS + W));
        ov[0] = __ldg(reinterpret_cast<const float4*>(pO));
        ov[1] = __ldg(reinterpret_cast<const float4*>(pO + W));
        mv[0] = __ldg(reinterpret_cast<const float4*>(pM));
        mv[1] = __ldg(reinterpret_cast<const float4*>(pM + W));
        pO += DS; pM += DS;

        float s[4][XV], d[4][XV];
        xpass4(pI, c + 1 < D, r0ok, r3ok, xl, xr, s, d);

        // Per output row: fold -> step -> magnitude -> pair-exchange -> loss.
#pragma unroll
        for (int r = 0; r < YV; r++) {
            float A[XV], Bx[XV], By[XV], msq[XV], mag[XV], omag[XV];
            fold(s, d, r, A, Bx, By);
            step_row(st[r], A, Bx, By, msq);
#pragma unroll
            for (int j = 0; j < XV; j++) mag[j] = fsqrt_a(msq[j]);
#pragma unroll
            for (int j = 0; j < XV; j++) omag[j] = __shfl_xor_sync(0xffffffffu, mag[j], 1);

            const float ownv[XV] = { cv[r].x, cv[r].y, cv[r].z, cv[r].w };
            const float othv[XV] = { ov[r].x, ov[r].y, ov[r].z, ov[r].w };
            const float mvj[XV]  = { mv[r].x, mv[r].y, mv[r].z, mv[r].w };
            // Both lanes compute identical loss (signs cancel under squaring);
            // duplication compensated by the 0.5 factor at the end.
#pragma unroll
            for (int j = 0; j < XV; j++) {
                float dd  = ownv[j] - othv[j];
                float mse = dd * dd * mvj[j];
                float dm  = mag[j] - omag[j];
                float mge = dm * dm * mvj[j];
                acc += fmaf(htanh(mge), mse, mse);
            }
        }
    }
    acc *= 0.5f;

    // Block reduction (2 warps) -> one fp64 atomic; last block finalizes + re-arms
#pragma unroll
    for (int o = 16; o; o >>= 1) acc += __shfl_xor_sync(0xffffffffu, acc, o);
    __shared__ float ws[THREADS / 32];
    int lane = threadIdx.x & 31, wid = threadIdx.x >> 5;
    if (lane == 0) ws[wid] = acc;
    __syncthreads();
    if (threadIdx.x == 0) {
        float s = ws[0] + ws[1];
        atomicAdd(&g_accum, (double)s);
        __threadfence();
        unsigned tk = atomicAdd(&g_done, 1u);
        if (tk == (unsigned)gridDim.x - 1u) {
            double total = atomicAdd(&g_accum, 0.0);
            out[0] = (float)(total / (double)NVOX);
            g_accum = 0.0;
            g_done  = 0;
        }
    }
}

extern "C" void kernel_launch(void* const* d_in, const int* in_sizes, int n_in,
                              void* d_out, int out_size) {
    k_loss<<<NBLOCKS, THREADS>>>((const float*)d_in[0], (const float*)d_in[1],
                                 (const float*)d_in[2], (float*)d_out);
}

// round 16
// speedup vs baseline: 1.8293x; 1.8293x over previous
#include <cuda_runtime.h>

// Geometry fixed by the reference: (2,1,192,192,192) fp32 x3 -> scalar
constexpr int BATCH = 2, D = 192, H = 192, W = 192;
constexpr int DS = H * W;
constexpr int XV = 4;                  // x-values per lane (one float4)
constexpr int YV = 2;                  // output rows per lane
constexpr int ZC = 24;                 // z planes per lane
constexpr int GX = W / XV;             // 48
constexpr int GY = H / YV;             // 96
constexpr int NZ = D / ZC;             // 8
constexpr int THREADS = 64;            // small CTAs -> wave-tail smoothing
constexpr long long NVOX = (long long)BATCH * D * H * W;
constexpr int NBLOCKS = GX * GY * NZ * BATCH * 2 / THREADS;   // 2304

__device__ double   g_accum = 0.0;
__device__ unsigned g_done  = 0;

__device__ __forceinline__ float fsqrt_a(float x) {
    float y; asm("sqrt.approx.f32 %0, %1;" : "=f"(y) : "f"(x)); return y;
}
__device__ __forceinline__ float htanh(float x) {
    float y; asm("tanh.approx.f32 %0, %1;" : "=f"(y) : "f"(x)); return y;
}

// Streaming z-partials for one output row of one image (24 regs):
//   Am/Ac = A[c-1], A[c];  Ux/Cx = Bx[c-1]+2Bx[c], Bx[c];  Uy/Cy likewise.
struct State { float Am[XV], Ac[XV], Ux[XV], Cx[XV], Uy[XV], Cy[XV]; };

// x-pass for one row: s = [1,2,1]*x, d = x[+1]-x[-1], zero-padded OOB.
// Halos are independent scalar LDGs (uncoupled issue -> full MLP).
__device__ __forceinline__ void row_sd(const float* __restrict__ p, bool ok, bool xl, bool xr,
                                       float s[XV], float d[XV], float* cen) {
    float v0 = 0.f, v1 = 0.f, v2 = 0.f, v3 = 0.f, vm = 0.f, vp = 0.f;
    if (ok) {
        float4 c = __ldg(reinterpret_cast<const float4*>(p));
        v0 = c.x; v1 = c.y; v2 = c.z; v3 = c.w;
        if (xl) vm = __ldg(p - 1);
        if (xr) vp = __ldg(p + XV);
    }
    s[0] = fmaf(2.f, v0, vm + v1);
    s[1] = fmaf(2.f, v1, v0 + v2);
    s[2] = fmaf(2.f, v2, v1 + v3);
    s[3] = fmaf(2.f, v3, v2 + vp);
    d[0] = v1 - vm;
    d[1] = v2 - v0;
    d[2] = v3 - v1;
    d[3] = vp - v2;
    if (cen) { cen[0] = v0; cen[1] = v1; cen[2] = v2; cen[3] = v3; }
}

// Load + x-pass the 4 input rows (gy0-1 .. gy0+2) of one plane.
__device__ __forceinline__ void xpass4(const float* __restrict__ pc, bool zok,
                                       bool r0ok, bool r3ok, bool xl, bool xr,
                                       float s[4][XV], float d[4][XV], float cenN[YV][XV]) {
    row_sd(pc - W,     zok && r0ok, xl, xr, s[0], d[0], nullptr);
    row_sd(pc,         zok,         xl, xr, s[1], d[1], cenN[0]);
    row_sd(pc + W,     zok,         xl, xr, s[2], d[2], cenN[1]);
    row_sd(pc + 2 * W, zok && r3ok, xl, xr, s[3], d[3], nullptr);
}

// y-fold for output row r (uses s/d rows r, r+1, r+2).
__device__ __forceinline__ void fold(const float s[4][XV], const float d[4][XV], int r,
                                     float A[XV], float Bx[XV], float By[XV]) {
#pragma unroll
    for (int j = 0; j < XV; j++) {
        A[j]  = fmaf(2.f, s[r + 1][j], s[r][j] + s[r + 2][j]);
        By[j] = s[r][j] - s[r + 2][j];
        Bx[j] = fmaf(2.f, d[r + 1][j], d[r][j] + d[r + 2][j]);
    }
}

__device__ __forceinline__ void state_init(State& st, const float A1[XV], const float Bx1[XV],
                                           const float By1[XV], const float A0[XV],
                                           const float Bx0[XV], const float By0[XV]) {
#pragma unroll
    for (int j = 0; j < XV; j++) {
        st.Am[j] = A1[j];  st.Ac[j] = A0[j];
        st.Ux[j] = fmaf(2.f, Bx0[j], Bx1[j]);  st.Cx[j] = Bx0[j];
        st.Uy[j] = fmaf(2.f, By0[j], By1[j]);  st.Cy[j] = By0[j];
    }
}

// z-combine at plane c given fresh plane c+1; advances streaming state.
__device__ __forceinline__ void step_row(State& st, const float A[XV], const float Bx[XV],
                                         const float By[XV], float msq[XV]) {
#pragma unroll
    for (int j = 0; j < XV; j++) {
        float gx = st.Ux[j] + Bx[j];
        float gy = st.Uy[j] + By[j];
        float gz = st.Am[j] - A[j];
        msq[j] = fmaf(gx, gx, fmaf(gy, gy, fmaf(gz, gz, 1e-10f)));
        st.Ux[j] = fmaf(2.f, Bx[j], st.Cx[j]);  st.Cx[j] = Bx[j];
        st.Uy[j] = fmaf(2.f, By[j], st.Cy[j]);  st.Cy[j] = By[j];
        st.Am[j] = st.Ac[j];                    st.Ac[j] = A[j];
    }
}

__global__ void __launch_bounds__(THREADS, 8)
k_loss(const float* __restrict__ pred,
       const float* __restrict__ gt,
       const float* __restrict__ mask,
       float* __restrict__ out) {
    const int gtid = blockIdx.x * THREADS + threadIdx.x;
    const int im = gtid & 1;          // 0: lane owns pred, 1: lane owns gt
    const int pr = gtid >> 1;         // pair index
    int xg  = pr % GX;
    int tq  = pr / GX;
    int yg  = tq % GY;  tq /= GY;
    int zc  = tq % NZ;
    int b   = tq / NZ;
    const int x0 = xg * XV, gy0 = yg * YV, z0 = zc * ZC;

    const bool r0ok = (gy0 > 0), r3ok = (gy0 + YV < H);
    const bool xl = (x0 > 0), xr = (x0 + XV < W);

    const float* ownBase = im ? gt : pred;
    const float* othBase = im ? pred : gt;
    const size_t cell = (size_t)b * D * DS + (size_t)gy0 * W + x0;

    const float* pI = ownBase + cell + (long long)(z0 - 1) * DS;  // own stencil walker
    const float* pO = othBase + cell + (long long)z0 * DS;        // other-image centers
    const float* pM = mask    + cell + (long long)z0 * DS;        // mask centers

    State st[YV];
    float cen[YV][XV];

    // Prologue: own image, planes z0-1 and z0
    {
        float s[4][XV], d[4][XV], cn[YV][XV];
        float A1[XV], Bx1[XV], By1[XV], A0[XV], Bx0[XV], By0[XV];
        xpass4(pI, z0 > 0, r0ok, r3ok, xl, xr, s, d, cn);
        pI += DS;
        float s2[4][XV], d2[4][XV];
        xpass4(pI, true, r0ok, r3ok, xl, xr, s2, d2, cen);
#pragma unroll
        for (int r = 0; r < YV; r++) {
            fold(s, d, r, A1, Bx1, By1);
            fold(s2, d2, r, A0, Bx0, By0);
            state_init(st[r], A1, Bx1, By1, A0, Bx0, By0);
        }
    }

    float acc = 0.f;
#pragma unroll 2
    for (int c = z0; c < z0 + ZC; c++) {
        pI += DS;                                  // own image, plane c+1
        // other-image / mask centers for plane c: independent loads, issued
        // early (latency hidden by the plane's row loads)
        float4 ov[YV], mv[YV];
        ov[0] = __ldg(reinterpret_cast<const float4*>(pO));
        ov[1] = __ldg(reinterpret_cast<const float4*>(pO + W));
        mv[0] = __ldg(reinterpret_cast<const float4*>(pM));
        mv[1] = __ldg(reinterpret_cast<const float4*>(pM + W));
        pO += DS; pM += DS;

        float s[4][XV], d[4][XV], cenN[YV][XV];
        xpass4(pI, c + 1 < D, r0ok, r3ok, xl, xr, s, d, cenN);

        // Per output row: fold -> step -> magnitude -> pair-exchange -> loss.
#pragma unroll
        for (int r = 0; r < YV; r++) {
            float A[XV], Bx[XV], By[XV], msq[XV], mag[XV], omag[XV];
            fold(s, d, r, A, Bx, By);
            step_row(st[r], A, Bx, By, msq);
#pragma unroll
            for (int j = 0; j < XV; j++) mag[j] = fsqrt_a(msq[j]);
#pragma unroll
            for (int j = 0; j < XV; j++) omag[j] = __shfl_xor_sync(0xffffffffu, mag[j], 1);

            const float othv[XV] = { ov[r].x, ov[r].y, ov[r].z, ov[r].w };
            const float mvj[XV]  = { mv[r].x, mv[r].y, mv[r].z, mv[r].w };
            // Both lanes compute identical loss (signs cancel under squaring);
            // the duplication is compensated by the 0.5 factor at the end.
#pragma unroll
            for (int j = 0; j < XV; j++) {
                float dd  = cen[r][j] - othv[j];
                float mse = dd * dd * mvj[j];
                float dm  = mag[j] - omag[j];
                float mge = dm * dm * mvj[j];
                acc += fmaf(htanh(mge), mse, mse);
            }
#pragma unroll
            for (int j = 0; j < XV; j++) cen[r][j] = cenN[r][j];
        }
    }
    acc *= 0.5f;

    // Block reduction (2 warps) -> one fp64 atomic; last block finalizes + re-arms
#pragma unroll
    for (int o = 16; o; o >>= 1) acc += __shfl_xor_sync(0xffffffffu, acc, o);
    __shared__ float ws[THREADS / 32];
    int lane = threadIdx.x & 31, wid = threadIdx.x >> 5;
    if (lane == 0) ws[wid] = acc;
    __syncthreads();
    if (threadIdx.x == 0) {
        float s = ws[0] + ws[1];
        atomicAdd(&g_accum, (double)s);
        __threadfence();
        unsigned tk = atomicAdd(&g_done, 1u);
        if (tk == (unsigned)gridDim.x - 1u) {
            double total = atomicAdd(&g_accum, 0.0);
            out[0] = (float)(total / (double)NVOX);
            g_accum = 0.0;
            g_done  = 0;
        }
    }
}

extern "C" void kernel_launch(void* const* d_in, const int* in_sizes, int n_in,
                              void* d_out, int out_size) {
    k_loss<<<NBLOCKS, THREADS>>>((const float*)d_in[0], (const float*)d_in[1],
                                 (const float*)d_in[2], (float*)d_out);
}

// round 17
// speedup vs baseline: 1.8828x; 1.0292x over previous
#include <cuda_runtime.h>

// Geometry fixed by the reference: (2,1,192,192,192) fp32 x3 -> scalar
constexpr int BATCH = 2, D = 192, H = 192, W = 192;
constexpr int DS = H * W;
constexpr int XV = 4;                  // x-values per lane (one float4)
constexpr int YV = 2;                  // output rows per lane
constexpr int ZC = 24;                 // z planes per lane
constexpr int GX = W / XV;             // 48
constexpr int GY = H / YV;             // 96
constexpr int NZ = D / ZC;             // 8
constexpr int THREADS = 64;            // small CTAs -> wave-tail smoothing
constexpr long long NVOX = (long long)BATCH * D * H * W;
constexpr int NBLOCKS = GX * GY * NZ * BATCH * 2 / THREADS;   // 2304

__device__ double   g_accum = 0.0;
__device__ unsigned g_done  = 0;

__device__ __forceinline__ float fsqrt_a(float x) {
    float y; asm("sqrt.approx.f32 %0, %1;" : "=f"(y) : "f"(x)); return y;
}
__device__ __forceinline__ float htanh(float x) {
    float y; asm("tanh.approx.f32 %0, %1;" : "=f"(y) : "f"(x)); return y;
}
// Streaming (evict-first) float4 load for read-once data (mask): keeps L2
// capacity for the pred/gt stencil rows that ARE reused across CTAs.
__device__ __forceinline__ float4 ldcs4(const float4* p) {
    float4 v;
    asm("ld.global.cs.v4.f32 {%0,%1,%2,%3}, [%4];"
        : "=f"(v.x), "=f"(v.y), "=f"(v.z), "=f"(v.w) : "l"(p));
    return v;
}

// Streaming z-partials for one output row of one image (24 regs):
//   Am/Ac = A[c-1], A[c];  Ux/Cx = Bx[c-1]+2Bx[c], Bx[c];  Uy/Cy likewise.
struct State { float Am[XV], Ac[XV], Ux[XV], Cx[XV], Uy[XV], Cy[XV]; };

// x-pass for one row: s = [1,2,1]*x, d = x[+1]-x[-1], zero-padded OOB.
// Halos are independent scalar LDGs (uncoupled issue -> full MLP).
__device__ __forceinline__ void row_sd(const float* __restrict__ p, bool ok, bool xl, bool xr,
                                       float s[XV], float d[XV], float* cen) {
    float v0 = 0.f, v1 = 0.f, v2 = 0.f, v3 = 0.f, vm = 0.f, vp = 0.f;
    if (ok) {
        float4 c = __ldg(reinterpret_cast<const float4*>(p));
        v0 = c.x; v1 = c.y; v2 = c.z; v3 = c.w;
        if (xl) vm = __ldg(p - 1);
        if (xr) vp = __ldg(p + XV);
    }
    s[0] = fmaf(2.f, v0, vm + v1);
    s[1] = fmaf(2.f, v1, v0 + v2);
    s[2] = fmaf(2.f, v2, v1 + v3);
    s[3] = fmaf(2.f, v3, v2 + vp);
    d[0] = v1 - vm;
    d[1] = v2 - v0;
    d[2] = v3 - v1;
    d[3] = vp - v2;
    if (cen) { cen[0] = v0; cen[1] = v1; cen[2] = v2; cen[3] = v3; }
}

// Load + x-pass the 4 input rows (gy0-1 .. gy0+2) of one plane.
__device__ __forceinline__ void xpass4(const float* __restrict__ pc, bool zok,
                                       bool r0ok, bool r3ok, bool xl, bool xr,
                                       float s[4][XV], float d[4][XV], float cenN[YV][XV]) {
    row_sd(pc - W,     zok && r0ok, xl, xr, s[0], d[0], nullptr);
    row_sd(pc,         zok,         xl, xr, s[1], d[1], cenN[0]);
    row_sd(pc + W,     zok,         xl, xr, s[2], d[2], cenN[1]);
    row_sd(pc + 2 * W, zok && r3ok, xl, xr, s[3], d[3], nullptr);
}

// y-fold for output row r (uses s/d rows r, r+1, r+2).
__device__ __forceinline__ void fold(const float s[4][XV], const float d[4][XV], int r,
                                     float A[XV], float Bx[XV], float By[XV]) {
#pragma unroll
    for (int j = 0; j < XV; j++) {
        A[j]  = fmaf(2.f, s[r + 1][j], s[r][j] + s[r + 2][j]);
        By[j] = s[r][j] - s[r + 2][j];
        Bx[j] = fmaf(2.f, d[r + 1][j], d[r][j] + d[r + 2][j]);
    }
}

__device__ __forceinline__ void state_init(State& st, const float A1[XV], const float Bx1[XV],
                                           const float By1[XV], const float A0[XV],
                                           const float Bx0[XV], const float By0[XV]) {
#pragma unroll
    for (int j = 0; j < XV; j++) {
        st.Am[j] = A1[j];  st.Ac[j] = A0[j];
        st.Ux[j] = fmaf(2.f, Bx0[j], Bx1[j]);  st.Cx[j] = Bx0[j];
        st.Uy[j] = fmaf(2.f, By0[j], By1[j]);  st.Cy[j] = By0[j];
    }
}

// z-combine at plane c given fresh plane c+1; advances streaming state.
__device__ __forceinline__ void step_row(State& st, const float A[XV], const float Bx[XV],
                                         const float By[XV], float msq[XV]) {
#pragma unroll
    for (int j = 0; j < XV; j++) {
        float gx = st.Ux[j] + Bx[j];
        float gy = st.Uy[j] + By[j];
        float gz = st.Am[j] - A[j];
        msq[j] = fmaf(gx, gx, fmaf(gy, gy, fmaf(gz, gz, 1e-10f)));
        st.Ux[j] = fmaf(2.f, Bx[j], st.Cx[j]);  st.Cx[j] = Bx[j];
        st.Uy[j] = fmaf(2.f, By[j], st.Cy[j]);  st.Cy[j] = By[j];
        st.Am[j] = st.Ac[j];                    st.Ac[j] = A[j];
    }
}

__global__ void __launch_bounds__(THREADS, 8)
k_loss(const float* __restrict__ pred,
       const float* __restrict__ gt,
       const float* __restrict__ mask,
       float* __restrict__ out) {
    const int gtid = blockIdx.x * THREADS + threadIdx.x;
    const int im = gtid & 1;          // 0: lane owns pred, 1: lane owns gt
    const int pr = gtid >> 1;         // pair index
    int xg  = pr % GX;
    int tq  = pr / GX;
    int yg  = tq % GY;  tq /= GY;
    int zc  = tq % NZ;
    int b   = tq / NZ;
    const int x0 = xg * XV, gy0 = yg * YV, z0 = zc * ZC;

    const bool r0ok = (gy0 > 0), r3ok = (gy0 + YV < H);
    const bool xl = (x0 > 0), xr = (x0 + XV < W);

    const float* ownBase = im ? gt : pred;
    const float* othBase = im ? pred : gt;
    const size_t cell = (size_t)b * D * DS + (size_t)gy0 * W + x0;

    const float* pI = ownBase + cell + (long long)(z0 - 1) * DS;  // own stencil walker
    const float* pO = othBase + cell + (long long)z0 * DS;        // other-image centers
    const float* pM = mask    + cell + (long long)z0 * DS;        // mask centers

    State st[YV];
    float cen[YV][XV];

    // Prologue: own image, planes z0-1 and z0
    {
        float s[4][XV], d[4][XV], cn[YV][XV];
        float A1[XV], Bx1[XV], By1[XV], A0[XV], Bx0[XV], By0[XV];
        xpass4(pI, z0 > 0, r0ok, r3ok, xl, xr, s, d, cn);
        pI += DS;
        float s2[4][XV], d2[4][XV];
        xpass4(pI, true, r0ok, r3ok, xl, xr, s2, d2, cen);
#pragma unroll
        for (int r = 0; r < YV; r++) {
            fold(s, d, r, A1, Bx1, By1);
            fold(s2, d2, r, A0, Bx0, By0);
            state_init(st[r], A1, Bx1, By1, A0, Bx0, By0);
        }
    }

    float acc = 0.f;
#pragma unroll 2
    for (int c = z0; c < z0 + ZC; c++) {
        pI += DS;                                  // own image, plane c+1
        // other-image centers: cached loads (L1/L2 hits via partner's stencil
        // traffic). Mask: STREAMING loads -- read-once data must not evict
        // the reused pred/gt rows from L2.
        float4 ov[YV], mv[YV];
        ov[0] = __ldg(reinterpret_cast<const float4*>(pO));
        ov[1] = __ldg(reinterpret_cast<const float4*>(pO + W));
        mv[0] = ldcs4(reinterpret_cast<const float4*>(pM));
        mv[1] = ldcs4(reinterpret_cast<const float4*>(pM + W));
        pO += DS; pM += DS;

        float s[4][XV], d[4][XV], cenN[YV][XV];
        xpass4(pI, c + 1 < D, r0ok, r3ok, xl, xr, s, d, cenN);

        // Per output row: fold -> step -> magnitude -> pair-exchange -> loss.
#pragma unroll
        for (int r = 0; r < YV; r++) {
            float A[XV], Bx[XV], By[XV], msq[XV], mag[XV], omag[XV];
            fold(s, d, r, A, Bx, By);
            step_row(st[r], A, Bx, By, msq);
#pragma unroll
            for (int j = 0; j < XV; j++) mag[j] = fsqrt_a(msq[j]);
#pragma unroll
            for (int j = 0; j < XV; j++) omag[j] = __shfl_xor_sync(0xffffffffu, mag[j], 1);

            const float othv[XV] = { ov[r].x, ov[r].y, ov[r].z, ov[r].w };
            const float mvj[XV]  = { mv[r].x, mv[r].y, mv[r].z, mv[r].w };
            // Both lanes compute identical loss (signs cancel under squaring);
            // the duplication is compensated by the 0.5 factor at the end.
#pragma unroll
            for (int j = 0; j < XV; j++) {
                float dd  = cen[r][j] - othv[j];
                float mse = dd * dd * mvj[j];
                float dm  = mag[j] - omag[j];
                float mge = dm * dm * mvj[j];
                acc += fmaf(htanh(mge), mse, mse);
            }
#pragma unroll
            for (int j = 0; j < XV; j++) cen[r][j] = cenN[r][j];
        }
    }
    acc *= 0.5f;

    // Block reduction (2 warps) -> one fp64 atomic; last block finalizes + re-arms
#pragma unroll
    for (int o = 16; o; o >>= 1) acc += __shfl_xor_sync(0xffffffffu, acc, o);
    __shared__ float ws[THREADS / 32];
    int lane = threadIdx.x & 31, wid = threadIdx.x >> 5;
    if (lane == 0) ws[wid] = acc;
    __syncthreads();
    if (threadIdx.x == 0) {
        float s = ws[0] + ws[1];
        atomicAdd(&g_accum, (double)s);
        __threadfence();
        unsigned tk = atomicAdd(&g_done, 1u);
        if (tk == (unsigned)gridDim.x - 1u) {
            double total = atomicAdd(&g_accum, 0.0);
            out[0] = (float)(total / (double)NVOX);
            g_accum = 0.0;
            g_done  = 0;
        }
    }
}

extern "C" void kernel_launch(void* const* d_in, const int* in_sizes, int n_in,
                              void* d_out, int out_size) {
    k_loss<<<NBLOCKS, THREADS>>>((const float*)d_in[0], (const float*)d_in[1],
                                 (const float*)d_in[2], (float*)d_out);
}